// round 13
// baseline (speedup 1.0000x reference)
#include <cuda_runtime.h>

#define BATCHN 8
#define SEQ    2048
#define DIM    1024
#define NS     16
#define ROWS   (BATCHN*SEQ)     // 16384
#define LCH    32               // chunk length
#define CPB    (SEQ/LCH)        // 64 chunks per batch
#define NCHUNK (BATCHN*CPB)     // 512 chunks
#define NHALF  (ROWS/16)        // 1024 half-chunks
#define GPB    8                // supergroups per batch
#define CPG    (CPB/GPB)        // 8 chunks per supergroup
#define NGRP   (BATCHN*GPB)     // 64 supergroups
#define NTERMS 21               // Taylor degree 20
#define THETA  5.2f
#define MS     260              // shared matrix slot stride (floats)

// ---------------- scratch (static device globals; no runtime alloc) ----------------
__device__ float g_Anorm;
__device__ __align__(128) float g_Pd[NTERMS*256];              // A^k / k!
__device__ __align__(128) float g_Bu[ROWS*NS];
__device__ __align__(128) float g_AexpT[(size_t)ROWS*NS*NS];   // 16 MB, E^T per row
__device__ __align__(128) float g_PTh[NHALF*NS*NS];            // half-chunk product (transposed rep)
__device__ __align__(128) float g_eh[NHALF*NS];                // half-chunk end-state
__device__ __align__(128) float g_PT[NCHUNK*NS*NS];            // chunk product
__device__ __align__(128) float g_e[NCHUNK*NS];                // chunk end-state
__device__ __align__(128) float g_PTs[NGRP*NS*NS];             // supergroup product
__device__ __align__(128) float g_es[NGRP*NS];                 // supergroup end-state
__device__ __align__(128) float g_hsuper[NGRP*NS];             // state at supergroup start
__device__ __align__(128) float g_hs[(size_t)ROWS*NS];

// ---------------- f32x2 helpers ----------------
__device__ __forceinline__ unsigned long long pk2(float lo, float hi) {
    unsigned long long r;
    asm("mov.b64 %0, {%1, %2};" : "=l"(r) : "f"(lo), "f"(hi));
    return r;
}
__device__ __forceinline__ float2 upk2(unsigned long long v) {
    float2 r;
    asm("mov.b64 {%0, %1}, %2;" : "=f"(r.x), "=f"(r.y) : "l"(v));
    return r;
}
__device__ __forceinline__ void fma2(unsigned long long& d, unsigned long long a, unsigned long long b) {
    asm("fma.rn.f32x2 %0, %1, %2, %0;" : "+l"(d) : "l"(a), "l"(b));
}

// ---------------- combine: S_out = S_R @ S_L, e_out = S_R e_L + e_R ----------------
__device__ __forceinline__ void comb(float* Em, float* es, int sL, int sR, int sO, int i) {
    const float* A = &Em[sR*MS + i*16];
    const float* B = &Em[sL*MS];
    float a[16];
    #pragma unroll
    for (int k = 0; k < 16; k++) a[k] = A[k];
    float4 c0 = make_float4(0,0,0,0), c1 = c0, c2 = c0, c3 = c0;
    #pragma unroll
    for (int k = 0; k < 16; k++) {
        const float4* bk = (const float4*)(B + k*16);
        float4 b0 = bk[0], b1 = bk[1], b2 = bk[2], b3 = bk[3];
        float w = a[k];
        c0.x = fmaf(w, b0.x, c0.x); c0.y = fmaf(w, b0.y, c0.y);
        c0.z = fmaf(w, b0.z, c0.z); c0.w = fmaf(w, b0.w, c0.w);
        c1.x = fmaf(w, b1.x, c1.x); c1.y = fmaf(w, b1.y, c1.y);
        c1.z = fmaf(w, b1.z, c1.z); c1.w = fmaf(w, b1.w, c1.w);
        c2.x = fmaf(w, b2.x, c2.x); c2.y = fmaf(w, b2.y, c2.y);
        c2.z = fmaf(w, b2.z, c2.z); c2.w = fmaf(w, b2.w, c2.w);
        c3.x = fmaf(w, b3.x, c3.x); c3.y = fmaf(w, b3.y, c3.y);
        c3.z = fmaf(w, b3.z, c3.z); c3.w = fmaf(w, b3.w, c3.w);
    }
    const float* eL = &es[sL*17];
    float ev = es[sR*17 + i];
    #pragma unroll
    for (int k = 0; k < 16; k++) ev = fmaf(a[k], eL[k], ev);
    float4* C4 = (float4*)&Em[sO*MS + i*16];
    C4[0] = c0; C4[1] = c1; C4[2] = c2; C4[3] = c3;
    es[sO*17 + i] = ev;
}

// ---------------- kernel 0: A = -exp(A_log), inf-norm, P_k = A^k/k! ----------------
__global__ __launch_bounds__(256) void k_prepA(const float* __restrict__ A_log) {
    __shared__ float As[256];
    __shared__ float buf[2][256];
    __shared__ float rowsum[NS];
    int tid = threadIdx.x;
    int i = tid >> 4, j = tid & 15;
    float a = -expf(A_log[tid]);
    As[tid] = a;
    __syncthreads();
    float Ac[16];
    #pragma unroll
    for (int k = 0; k < 16; k++) Ac[k] = As[k*16 + j];
    if (tid < NS) {
        float s = 0.f;
        #pragma unroll
        for (int c = 0; c < NS; c++) s += fabsf(As[tid*16 + c]);
        rowsum[tid] = s;
    }
    __syncthreads();
    if (tid == 0) {
        float m = 0.f;
        #pragma unroll
        for (int r = 0; r < NS; r++) m = fmaxf(m, rowsum[r]);
        g_Anorm = m;
    }
    float id = (i == j) ? 1.f : 0.f;
    buf[0][tid] = id;
    g_Pd[tid] = id;
    __syncthreads();
    int cur = 0;
    for (int k = 1; k < NTERMS; k++) {
        const float* row = &buf[cur][i*16];
        float a0 = fmaf(row[0], Ac[0], fmaf(row[1], Ac[1], fmaf(row[2], Ac[2], row[3]*Ac[3])));
        float a1 = fmaf(row[4], Ac[4], fmaf(row[5], Ac[5], fmaf(row[6], Ac[6], row[7]*Ac[7])));
        float a2 = fmaf(row[8], Ac[8], fmaf(row[9], Ac[9], fmaf(row[10], Ac[10], row[11]*Ac[11])));
        float a3 = fmaf(row[12], Ac[12], fmaf(row[13], Ac[13], fmaf(row[14], Ac[14], row[15]*Ac[15])));
        float acc = ((a0 + a1) + (a2 + a3)) * (1.f / (float)k);
        buf[cur ^ 1][tid] = acc;
        g_Pd[k*256 + tid] = acc;
        cur ^= 1;
        __syncthreads();
    }
}

// ---------------- kernel 1b: Bu = u @ B_mat, register-tiled + f32x2 ----------------
__global__ __launch_bounds__(256, 1) void k_bu(const float* __restrict__ u,
                                               const float* __restrict__ B) {
    __shared__ __align__(16) float usb[128*33];
    __shared__ __align__(16) float Bst[16*34];
    int tid  = threadIdx.x;
    int ks   = tid >> 7;
    int ngrp = (tid >> 6) & 1;
    int rowp = tid & 63;
    int r0   = blockIdx.x * 128;

    unsigned long long a0[8], a1[8];
    #pragma unroll
    for (int nn = 0; nn < 8; nn++) { a0[nn] = 0ull; a1[nn] = 0ull; }

    int lrow = tid >> 3, lq = tid & 7;
    int bkk  = tid >> 3, bnp = tid & 7;
    float4 pu[4]; float2 pb;
    #pragma unroll
    for (int it = 0; it < 4; it++)
        pu[it] = *(const float4*)&u[(size_t)(r0 + lrow + it*32) * DIM + lq*4];
    pb = *(const float2*)&B[(size_t)bkk * NS + bnp*2];

    for (int t = 0; t < 32; t++) {
        #pragma unroll
        for (int it = 0; it < 4; it++) {
            int row = lrow + it*32;
            usb[row*33 + lq*4 + 0] = pu[it].x;
            usb[row*33 + lq*4 + 1] = pu[it].y;
            usb[row*33 + lq*4 + 2] = pu[it].z;
            usb[row*33 + lq*4 + 3] = pu[it].w;
        }
        Bst[(2*bnp + 0)*34 + bkk] = pb.x;
        Bst[(2*bnp + 1)*34 + bkk] = pb.y;
        __syncthreads();
        if (t + 1 < 32) {
            int kt = (t + 1) * 32;
            #pragma unroll
            for (int it = 0; it < 4; it++)
                pu[it] = *(const float4*)&u[(size_t)(r0 + lrow + it*32) * DIM + kt + lq*4];
            pb = *(const float2*)&B[(size_t)(kt + bkk) * NS + bnp*2];
        }
        int kb = ks * 16;
        #pragma unroll
        for (int kk = 0; kk < 8; kk++) {
            int k = kb + 2*kk;
            unsigned long long ua = *(const unsigned long long*)&usb[(2*rowp)*33 + k];
            const float* ur1 = &usb[(2*rowp + 1)*33 + k];
            unsigned long long ub = pk2(ur1[0], ur1[1]);
            #pragma unroll
            for (int nn = 0; nn < 8; nn++) {
                unsigned long long bb = *(const unsigned long long*)&Bst[(8*ngrp + nn)*34 + k];
                fma2(a0[nn], ua, bb);
                fma2(a1[nn], ub, bb);
            }
        }
        __syncthreads();
    }
    float* red = usb;
    if (ks == 1) {
        int p = tid - 128;
        #pragma unroll
        for (int nn = 0; nn < 8; nn++) {
            float2 x0 = upk2(a0[nn]); float2 x1 = upk2(a1[nn]);
            red[p*16 + nn]     = x0.x + x0.y;
            red[p*16 + 8 + nn] = x1.x + x1.y;
        }
    }
    __syncthreads();
    if (ks == 0) {
        #pragma unroll
        for (int nn = 0; nn < 8; nn++) {
            float2 x0 = upk2(a0[nn]); float2 x1 = upk2(a1[nn]);
            float v0 = x0.x + x0.y + red[tid*16 + nn];
            float v1 = x1.x + x1.y + red[tid*16 + 8 + nn];
            g_Bu[(size_t)(r0 + 2*rowp)     * NS + 8*ngrp + nn] = v0;
            g_Bu[(size_t)(r0 + 2*rowp + 1) * NS + 8*ngrp + nn] = v1;
        }
    }
}

// ---------------- kernel 2: fused delta + expm + half-chunk product tree ----------------
// Block = 16 rows = one half-chunk. Writes g_AexpT (for scan) + (P,e) of the half-chunk.
__global__ __launch_bounds__(256, 1) void k_expm(const float* __restrict__ gate,
                                                 const float* __restrict__ dt_w,
                                                 const float* __restrict__ dt_b) {
    __shared__ float Ts[16*257];
    __shared__ __align__(16) float Em2[24*MS];
    __shared__ float es2[24*17];
    __shared__ float ys[16];
    __shared__ int   ss[16];
    int tid = threadIdx.x;
    int hc  = blockIdx.x;
    int r0  = hc * 16;
    int wid = tid >> 5, lane = tid & 31;
    const float4* w4 = (const float4*)dt_w;
    float anorm = g_Anorm;
    float b0 = dt_b[0];
    #pragma unroll
    for (int rr = 0; rr < 2; rr++) {
        int row = r0 + 2*wid + rr;
        const float4* g4 = (const float4*)(gate + (size_t)row * DIM);
        float acc = 0.f;
        #pragma unroll
        for (int ii = 0; ii < 8; ii++) {
            float4 g = g4[lane + 32*ii];
            float4 w = w4[lane + 32*ii];
            acc += g.x*w.x + g.y*w.y + g.z*w.z + g.w*w.w;
        }
        #pragma unroll
        for (int o = 16; o; o >>= 1) acc += __shfl_xor_sync(0xffffffffu, acc, o);
        if (lane == 0) {
            float d = 1.f / (1.f + expf(-(acc + b0)));
            float nn = d * anorm;
            int s = 0;
            while (nn > THETA) { nn *= 0.5f; s++; }
            ss[2*wid + rr] = s;
            ys[2*wid + rr] = ldexpf(d, -s);
        }
    }
    float p[NTERMS];
    #pragma unroll
    for (int k = 0; k < NTERMS; k++) p[k] = g_Pd[k*256 + tid];
    __syncthreads();
    #pragma unroll
    for (int r = 0; r < 16; r++) {
        float y = ys[r];
        float acc = p[NTERMS-1];
        #pragma unroll
        for (int k = NTERMS-2; k >= 0; k--) acc = acc*y + p[k];
        Ts[r*257 + tid] = acc;
    }
    __syncthreads();
    int r = tid >> 4, j = tid & 15;
    float v[16];
    #pragma unroll
    for (int i = 0; i < 16; i++) v[i] = Ts[r*257 + i*16 + j];   // v = column j of T for row r
    int s = ss[r];
    int smax = max(s, __shfl_xor_sync(0xffffffffu, s, 16));
    for (int q = 0; q < smax; q++) {
        float nv[16];
        #pragma unroll
        for (int i = 0; i < 16; i++) nv[i] = 0.f;
        #pragma unroll
        for (int k = 0; k < 16; k++) {
            float w = v[k];
            #pragma unroll
            for (int i = 0; i < 16; i++)
                nv[i] += __shfl_sync(0xffffffffu, v[i], k, 16) * w;
        }
        if (q < s) {
            #pragma unroll
            for (int i = 0; i < 16; i++) v[i] = nv[i];
        }
    }
    // write E^T for k_scan; stage S-rows into smem tree leaves (slot r, row j)
    float4 w0 = make_float4(v[0], v[1], v[2], v[3]);
    float4 w1 = make_float4(v[4], v[5], v[6], v[7]);
    float4 w2 = make_float4(v[8], v[9], v[10], v[11]);
    float4 w3 = make_float4(v[12], v[13], v[14], v[15]);
    float4* o = (float4*)(g_AexpT + (size_t)(r0 + r) * 256 + j * 16);
    o[0] = w0; o[1] = w1; o[2] = w2; o[3] = w3;
    float4* t4 = (float4*)&Em2[r*MS + j*16];
    t4[0] = w0; t4[1] = w1; t4[2] = w2; t4[3] = w3;
    es2[r*17 + j] = g_Bu[(size_t)(r0 + r) * NS + j];
    __syncthreads();
    // 4-level tree over 16 leaves (time order: lower slot = earlier)
    int q = tid >> 4, i = tid & 15;
    if (tid < 128) comb(Em2, es2, 2*q, 2*q + 1, 16 + q, i);
    __syncthreads();
    if (tid < 64)  comb(Em2, es2, 16 + 2*q, 16 + 2*q + 1, q, i);
    __syncthreads();
    if (tid < 32)  comb(Em2, es2, 2*q, 2*q + 1, 8 + q, i);
    __syncthreads();
    if (tid < 16)  comb(Em2, es2, 8, 9, 10, i);
    __syncthreads();
    g_PTh[hc * 256 + tid] = Em2[10*MS + tid];
    if (tid < 16) g_eh[hc * NS + tid] = es2[10*17 + tid];
}

// ---------------- kernel 3a: supergroup tree over 16 half-chunks; emits chunk + group (P,e) ----------------
__global__ __launch_bounds__(256) void k_super() {
    __shared__ __align__(16) float Em[24*MS];
    __shared__ float es[24*17];
    int g = blockIdx.x, tid = threadIdx.x;
    int hc0 = g * 16;
    int gc0 = g * CPG;
    int q = tid >> 4, i = tid & 15;
    #pragma unroll
    for (int t = 0; t < 16; t++)
        Em[t*MS + tid] = g_PTh[(hc0 + t)*256 + tid];
    es[q*17 + i] = g_eh[(hc0 + q)*NS + i];
    __syncthreads();
    // L1: half-chunk pairs -> chunk products (slots 16..23)
    if (tid < 128) comb(Em, es, 2*q, 2*q + 1, 16 + q, i);
    __syncthreads();
    #pragma unroll
    for (int c = 0; c < 8; c++)
        g_PT[(gc0 + c)*256 + tid] = Em[(16 + c)*MS + tid];
    if (tid < 128) g_e[gc0*NS + tid] = es[(16 + (tid >> 4))*17 + (tid & 15)];
    // L2..L4
    if (tid < 64)  comb(Em, es, 16 + 2*q, 16 + 2*q + 1, q, i);
    __syncthreads();
    if (tid < 32)  comb(Em, es, 2*q, 2*q + 1, 8 + q, i);
    __syncthreads();
    if (tid < 16)  comb(Em, es, 8, 9, 10, i);
    __syncthreads();
    g_PTs[g*256 + tid] = Em[10*MS + tid];
    if (tid < 16) g_es[g*NS + tid] = es[10*17 + tid];
}

// ---------------- kernel 3b: serial combine over 8 supergroups per batch ----------------
__global__ __launch_bounds__(256, 1) void k_comb2() {
    int tid  = threadIdx.x;
    int b    = tid >> 5;
    int lane = tid & 31;
    int m    = lane & 15;
    float h = 0.f;
    int g0 = b * GPB;
    float4 P4[4][4]; float ee[4];
    #pragma unroll
    for (int k = 0; k < 4; k++) {
        const float4* p4 = (const float4*)(g_PTs + (g0 + k) * 256 + m * NS);
        P4[k][0] = p4[0]; P4[k][1] = p4[1]; P4[k][2] = p4[2]; P4[k][3] = p4[3];
        ee[k] = g_es[(g0 + k) * NS + m];
    }
    #pragma unroll
    for (int c = 0; c < GPB; c++) {
        int sl = c & 3;
        int g = g0 + c;
        if (lane < NS) g_hsuper[g * NS + lane] = h;
        float4 p0 = P4[sl][0], p1 = P4[sl][1], p2 = P4[sl][2], p3 = P4[sl][3];
        float e = ee[sl];
        if (c + 4 < GPB) {
            const float4* n4 = (const float4*)(g_PTs + (g + 4) * 256 + m * NS);
            P4[sl][0] = n4[0]; P4[sl][1] = n4[1]; P4[sl][2] = n4[2]; P4[sl][3] = n4[3];
            ee[sl] = g_es[(g + 4) * NS + m];
        }
        float hv[NS];
        #pragma unroll
        for (int n = 0; n < NS; n++) hv[n] = __shfl_sync(0xffffffffu, h, n, 32);
        float t0 = fmaf(hv[0], p0.x, fmaf(hv[1], p0.y, fmaf(hv[2], p0.z, hv[3]*p0.w)));
        float t1 = fmaf(hv[4], p1.x, fmaf(hv[5], p1.y, fmaf(hv[6], p1.z, hv[7]*p1.w)));
        float t2 = fmaf(hv[8], p2.x, fmaf(hv[9], p2.y, fmaf(hv[10], p2.z, hv[11]*p2.w)));
        float t3 = fmaf(hv[12], p3.x, fmaf(hv[13], p3.y, fmaf(hv[14], p3.z, hv[15]*p3.w)));
        h = e + ((t0 + t1) + (t2 + t3));
    }
}

// ---------------- kernel 3c: scan; block = supergroup (8 warps), warp = chunk ----------------
// Each warp replays its prefix within the group (<=7 affine steps), then scans its chunk.
__global__ __launch_bounds__(256) void k_scan() {
    int g    = blockIdx.x;
    int wid  = threadIdx.x >> 5;
    int lane = threadIdx.x & 31;
    int m    = lane & 15;
    int gc   = g * CPG + wid;
    int r0   = gc * LCH;
    float h = g_hsuper[g * NS + m];
    // prefix replay: chunks [g*CPG, gc)
    for (int k = g * CPG; k < gc; k++) {
        const float4* p4 = (const float4*)(g_PT + k * 256 + m * NS);
        float4 p0 = p4[0], p1 = p4[1], p2 = p4[2], p3 = p4[3];
        float e = g_e[k * NS + m];
        float hv[NS];
        #pragma unroll
        for (int n = 0; n < NS; n++) hv[n] = __shfl_sync(0xffffffffu, h, n, 32);
        float t0 = fmaf(hv[0], p0.x, fmaf(hv[1], p0.y, fmaf(hv[2], p0.z, hv[3]*p0.w)));
        float t1 = fmaf(hv[4], p1.x, fmaf(hv[5], p1.y, fmaf(hv[6], p1.z, hv[7]*p1.w)));
        float t2 = fmaf(hv[8], p2.x, fmaf(hv[9], p2.y, fmaf(hv[10], p2.z, hv[11]*p2.w)));
        float t3 = fmaf(hv[12], p3.x, fmaf(hv[13], p3.y, fmaf(hv[14], p3.z, hv[15]*p3.w)));
        h = e + ((t0 + t1) + (t2 + t3));
    }
    const float4* base = (const float4*)(g_AexpT + (size_t)r0 * 256 + m * NS);
    float4 Ea[4][4]; float bub[4];
    #pragma unroll
    for (int k = 0; k < 4; k++) {
        const float4* p = base + (size_t)k * 64;
        Ea[k][0] = p[0]; Ea[k][1] = p[1]; Ea[k][2] = p[2]; Ea[k][3] = p[3];
        bub[k] = g_Bu[(size_t)(r0 + k) * NS + m];
    }
    #pragma unroll 4
    for (int t = 0; t < LCH; t++) {
        int sl = t & 3;
        float4 a0 = Ea[sl][0], a1 = Ea[sl][1], a2 = Ea[sl][2], a3 = Ea[sl][3];
        float bu = bub[sl];
        if (t + 4 < LCH) {
            const float4* p = base + (size_t)(t + 4) * 64;
            Ea[sl][0] = p[0]; Ea[sl][1] = p[1]; Ea[sl][2] = p[2]; Ea[sl][3] = p[3];
            bub[sl] = g_Bu[(size_t)(r0 + t + 4) * NS + m];
        }
        float hv[NS];
        #pragma unroll
        for (int n = 0; n < NS; n++) hv[n] = __shfl_sync(0xffffffffu, h, n, 32);
        float t0 = fmaf(hv[0], a0.x, fmaf(hv[1], a0.y, fmaf(hv[2], a0.z, hv[3]*a0.w)));
        float t1 = fmaf(hv[4], a1.x, fmaf(hv[5], a1.y, fmaf(hv[6], a1.z, hv[7]*a1.w)));
        float t2 = fmaf(hv[8], a2.x, fmaf(hv[9], a2.y, fmaf(hv[10], a2.z, hv[11]*a2.w)));
        float t3 = fmaf(hv[12], a3.x, fmaf(hv[13], a3.y, fmaf(hv[14], a3.z, hv[15]*a3.w)));
        h = bu + ((t0 + t1) + (t2 + t3));
        if (lane < NS) g_hs[(size_t)(r0 + t) * NS + m] = h;
    }
}

// ---------------- kernel 4: y = hs @ C^T + D*u (32 rows/block, float4 broadcast LDS) ----------------
__global__ __launch_bounds__(256) void k_out(const float* __restrict__ u,
                                             const float* __restrict__ C,
                                             const float* __restrict__ D,
                                             float* __restrict__ y) {
    __shared__ __align__(16) float hs_s[512];
    int tid = threadIdx.x;
    int d   = blockIdx.x * 256 + tid;
    int r0  = blockIdx.y * 32;
    hs_s[tid]       = g_hs[(size_t)r0 * NS + tid];
    hs_s[tid + 256] = g_hs[(size_t)r0 * NS + tid + 256];
    const float4* c4 = (const float4*)(C + (size_t)d * NS);
    float4 c0 = c4[0], c1 = c4[1], c2 = c4[2], c3 = c4[3];
    float Dd = D[d];
    float ucur = u[(size_t)r0 * DIM + d];
    __syncthreads();
    #pragma unroll 8
    for (int sl = 0; sl < 32; sl++) {
        float unext = 0.f;
        if (sl + 1 < 32) unext = u[(size_t)(r0 + sl + 1) * DIM + d];
        const float4* hp = (const float4*)(hs_s + sl * 16);
        float4 h0 = hp[0], h1 = hp[1], h2 = hp[2], h3 = hp[3];
        float t0 = fmaf(h0.x, c0.x, fmaf(h0.y, c0.y, fmaf(h0.z, c0.z, h0.w*c0.w)));
        float t1 = fmaf(h1.x, c1.x, fmaf(h1.y, c1.y, fmaf(h1.z, c1.z, h1.w*c1.w)));
        float t2 = fmaf(h2.x, c2.x, fmaf(h2.y, c2.y, fmaf(h2.z, c2.z, h2.w*c2.w)));
        float t3 = fmaf(h3.x, c3.x, fmaf(h3.y, c3.y, fmaf(h3.z, c3.z, h3.w*c3.w)));
        y[(size_t)(r0 + sl) * DIM + d] = Dd * ucur + ((t0 + t1) + (t2 + t3));
        ucur = unext;
    }
}

// ---------------- launch ----------------
extern "C" void kernel_launch(void* const* d_in, const int* in_sizes, int n_in,
                              void* d_out, int out_size) {
    const float* u     = (const float*)d_in[0];
    const float* gate  = (const float*)d_in[1];
    const float* A_log = (const float*)d_in[2];
    const float* B_mat = (const float*)d_in[3];
    const float* C_mat = (const float*)d_in[4];
    const float* D     = (const float*)d_in[5];
    const float* dt_w  = (const float*)d_in[6];
    const float* dt_b  = (const float*)d_in[7];
    float* y = (float*)d_out;

    k_prepA<<<1, 256>>>(A_log);
    k_bu<<<ROWS/128, 256>>>(u, B_mat);
    k_expm<<<NHALF, 256>>>(gate, dt_w, dt_b);
    k_super<<<NGRP, 256>>>();
    k_comb2<<<1, 256>>>();
    k_scan<<<NGRP, 256>>>();
    k_out<<<dim3(DIM/256, ROWS/32), 256>>>(u, C_mat, D, y);
}

// round 14
// speedup vs baseline: 1.0322x; 1.0322x over previous
#include <cuda_runtime.h>

#define BATCHN 8
#define SEQ    2048
#define DIM    1024
#define NS     16
#define ROWS   (BATCHN*SEQ)     // 16384
#define LCH    32               // chunk length
#define CPB    (SEQ/LCH)        // 64 chunks per batch
#define NCHUNK (BATCHN*CPB)     // 512 chunks
#define GPB    8                // supergroups per batch
#define CPG    (CPB/GPB)        // 8 chunks per supergroup
#define NGRP   (BATCHN*GPB)     // 64 supergroups
#define NTERMS 21               // Taylor degree 20
#define THETA  5.2f
#define MS     260              // shared matrix slot stride (floats)

// k_chunk dynamic smem: Em[48*MS] + es[48*17]
#define CHUNK_SMEM_BYTES ((48*MS + 48*17) * 4)

// ---------------- scratch (static device globals; no runtime alloc) ----------------
__device__ float g_Anorm;
__device__ __align__(128) float g_Pd[NTERMS*256];              // A^k / k!
__device__ __align__(128) float g_Bu[ROWS*NS];
__device__ __align__(128) float g_AexpT[(size_t)ROWS*NS*NS];   // 16 MB, E^T per row
__device__ __align__(128) float g_PT[NCHUNK*NS*NS];            // chunk product transposed
__device__ __align__(128) float g_e[NCHUNK*NS];                // chunk end-state
__device__ __align__(128) float g_PTs[NGRP*NS*NS];             // supergroup product
__device__ __align__(128) float g_es[NGRP*NS];                 // supergroup end-state
__device__ __align__(128) float g_hsuper[NGRP*NS];             // state at supergroup start
__device__ __align__(128) float g_hs[(size_t)ROWS*NS];

// ---------------- f32x2 helpers ----------------
__device__ __forceinline__ unsigned long long pk2(float lo, float hi) {
    unsigned long long r;
    asm("mov.b64 %0, {%1, %2};" : "=l"(r) : "f"(lo), "f"(hi));
    return r;
}
__device__ __forceinline__ float2 upk2(unsigned long long v) {
    float2 r;
    asm("mov.b64 {%0, %1}, %2;" : "=f"(r.x), "=f"(r.y) : "l"(v));
    return r;
}
__device__ __forceinline__ void fma2(unsigned long long& d, unsigned long long a, unsigned long long b) {
    asm("fma.rn.f32x2 %0, %1, %2, %0;" : "+l"(d) : "l"(a), "l"(b));
}

// ---------------- combine: S_out = S_R @ S_L, e_out = S_R e_L + e_R ----------------
__device__ __forceinline__ void comb(float* Em, float* es, int sL, int sR, int sO, int i) {
    const float* A = &Em[sR*MS + i*16];
    const float* B = &Em[sL*MS];
    float a[16];
    #pragma unroll
    for (int k = 0; k < 16; k++) a[k] = A[k];
    float4 c0 = make_float4(0,0,0,0), c1 = c0, c2 = c0, c3 = c0;
    #pragma unroll
    for (int k = 0; k < 16; k++) {
        const float4* bk = (const float4*)(B + k*16);
        float4 b0 = bk[0], b1 = bk[1], b2 = bk[2], b3 = bk[3];
        float w = a[k];
        c0.x = fmaf(w, b0.x, c0.x); c0.y = fmaf(w, b0.y, c0.y);
        c0.z = fmaf(w, b0.z, c0.z); c0.w = fmaf(w, b0.w, c0.w);
        c1.x = fmaf(w, b1.x, c1.x); c1.y = fmaf(w, b1.y, c1.y);
        c1.z = fmaf(w, b1.z, c1.z); c1.w = fmaf(w, b1.w, c1.w);
        c2.x = fmaf(w, b2.x, c2.x); c2.y = fmaf(w, b2.y, c2.y);
        c2.z = fmaf(w, b2.z, c2.z); c2.w = fmaf(w, b2.w, c2.w);
        c3.x = fmaf(w, b3.x, c3.x); c3.y = fmaf(w, b3.y, c3.y);
        c3.z = fmaf(w, b3.z, c3.z); c3.w = fmaf(w, b3.w, c3.w);
    }
    const float* eL = &es[sL*17];
    float ev = es[sR*17 + i];
    #pragma unroll
    for (int k = 0; k < 16; k++) ev = fmaf(a[k], eL[k], ev);
    float4* C4 = (float4*)&Em[sO*MS + i*16];
    C4[0] = c0; C4[1] = c1; C4[2] = c2; C4[3] = c3;
    es[sO*17 + i] = ev;
}

// ---------------- kernel 0: A = -exp(A_log), inf-norm, P_k = A^k/k! ----------------
__global__ __launch_bounds__(256) void k_prepA(const float* __restrict__ A_log) {
    __shared__ float As[256];
    __shared__ float buf[2][256];
    __shared__ float rowsum[NS];
    int tid = threadIdx.x;
    int i = tid >> 4, j = tid & 15;
    float a = -expf(A_log[tid]);
    As[tid] = a;
    __syncthreads();
    float Ac[16];
    #pragma unroll
    for (int k = 0; k < 16; k++) Ac[k] = As[k*16 + j];
    if (tid < NS) {
        float s = 0.f;
        #pragma unroll
        for (int c = 0; c < NS; c++) s += fabsf(As[tid*16 + c]);
        rowsum[tid] = s;
    }
    __syncthreads();
    if (tid == 0) {
        float m = 0.f;
        #pragma unroll
        for (int r = 0; r < NS; r++) m = fmaxf(m, rowsum[r]);
        g_Anorm = m;
    }
    float id = (i == j) ? 1.f : 0.f;
    buf[0][tid] = id;
    g_Pd[tid] = id;
    __syncthreads();
    int cur = 0;
    for (int k = 1; k < NTERMS; k++) {
        const float* row = &buf[cur][i*16];
        float a0 = fmaf(row[0], Ac[0], fmaf(row[1], Ac[1], fmaf(row[2], Ac[2], row[3]*Ac[3])));
        float a1 = fmaf(row[4], Ac[4], fmaf(row[5], Ac[5], fmaf(row[6], Ac[6], row[7]*Ac[7])));
        float a2 = fmaf(row[8], Ac[8], fmaf(row[9], Ac[9], fmaf(row[10], Ac[10], row[11]*Ac[11])));
        float a3 = fmaf(row[12], Ac[12], fmaf(row[13], Ac[13], fmaf(row[14], Ac[14], row[15]*Ac[15])));
        float acc = ((a0 + a1) + (a2 + a3)) * (1.f / (float)k);
        buf[cur ^ 1][tid] = acc;
        g_Pd[k*256 + tid] = acc;
        cur ^= 1;
        __syncthreads();
    }
}

// ---------------- kernel 1b: Bu = u @ B_mat, register-tiled + f32x2 ----------------
__global__ __launch_bounds__(256, 1) void k_bu(const float* __restrict__ u,
                                               const float* __restrict__ B) {
    __shared__ __align__(16) float usb[128*33];
    __shared__ __align__(16) float Bst[16*34];
    int tid  = threadIdx.x;
    int ks   = tid >> 7;
    int ngrp = (tid >> 6) & 1;
    int rowp = tid & 63;
    int r0   = blockIdx.x * 128;

    unsigned long long a0[8], a1[8];
    #pragma unroll
    for (int nn = 0; nn < 8; nn++) { a0[nn] = 0ull; a1[nn] = 0ull; }

    int lrow = tid >> 3, lq = tid & 7;
    int bkk  = tid >> 3, bnp = tid & 7;
    float4 pu[4]; float2 pb;
    #pragma unroll
    for (int it = 0; it < 4; it++)
        pu[it] = *(const float4*)&u[(size_t)(r0 + lrow + it*32) * DIM + lq*4];
    pb = *(const float2*)&B[(size_t)bkk * NS + bnp*2];

    for (int t = 0; t < 32; t++) {
        #pragma unroll
        for (int it = 0; it < 4; it++) {
            int row = lrow + it*32;
            usb[row*33 + lq*4 + 0] = pu[it].x;
            usb[row*33 + lq*4 + 1] = pu[it].y;
            usb[row*33 + lq*4 + 2] = pu[it].z;
            usb[row*33 + lq*4 + 3] = pu[it].w;
        }
        Bst[(2*bnp + 0)*34 + bkk] = pb.x;
        Bst[(2*bnp + 1)*34 + bkk] = pb.y;
        __syncthreads();
        if (t + 1 < 32) {
            int kt = (t + 1) * 32;
            #pragma unroll
            for (int it = 0; it < 4; it++)
                pu[it] = *(const float4*)&u[(size_t)(r0 + lrow + it*32) * DIM + kt + lq*4];
            pb = *(const float2*)&B[(size_t)(kt + bkk) * NS + bnp*2];
        }
        int kb = ks * 16;
        #pragma unroll
        for (int kk = 0; kk < 8; kk++) {
            int k = kb + 2*kk;
            unsigned long long ua = *(const unsigned long long*)&usb[(2*rowp)*33 + k];
            const float* ur1 = &usb[(2*rowp + 1)*33 + k];
            unsigned long long ub = pk2(ur1[0], ur1[1]);
            #pragma unroll
            for (int nn = 0; nn < 8; nn++) {
                unsigned long long bb = *(const unsigned long long*)&Bst[(8*ngrp + nn)*34 + k];
                fma2(a0[nn], ua, bb);
                fma2(a1[nn], ub, bb);
            }
        }
        __syncthreads();
    }
    float* red = usb;
    if (ks == 1) {
        int p = tid - 128;
        #pragma unroll
        for (int nn = 0; nn < 8; nn++) {
            float2 x0 = upk2(a0[nn]); float2 x1 = upk2(a1[nn]);
            red[p*16 + nn]     = x0.x + x0.y;
            red[p*16 + 8 + nn] = x1.x + x1.y;
        }
    }
    __syncthreads();
    if (ks == 0) {
        #pragma unroll
        for (int nn = 0; nn < 8; nn++) {
            float2 x0 = upk2(a0[nn]); float2 x1 = upk2(a1[nn]);
            float v0 = x0.x + x0.y + red[tid*16 + nn];
            float v1 = x1.x + x1.y + red[tid*16 + 8 + nn];
            g_Bu[(size_t)(r0 + 2*rowp)     * NS + 8*ngrp + nn] = v0;
            g_Bu[(size_t)(r0 + 2*rowp + 1) * NS + 8*ngrp + nn] = v1;
        }
    }
}

// ---------------- kernel 2: fused delta + expm (R11 proven) ----------------
__global__ __launch_bounds__(256, 1) void k_expm(const float* __restrict__ gate,
                                                 const float* __restrict__ dt_w,
                                                 const float* __restrict__ dt_b) {
    __shared__ float Ts[16*257];
    __shared__ float ys[16];
    __shared__ int   ss[16];
    int tid = threadIdx.x;
    int r0 = blockIdx.x * 16;
    int wid = tid >> 5, lane = tid & 31;
    const float4* w4 = (const float4*)dt_w;
    float anorm = g_Anorm;
    float b0 = dt_b[0];
    #pragma unroll
    for (int rr = 0; rr < 2; rr++) {
        int row = r0 + 2*wid + rr;
        const float4* g4 = (const float4*)(gate + (size_t)row * DIM);
        float acc = 0.f;
        #pragma unroll
        for (int ii = 0; ii < 8; ii++) {
            float4 g = g4[lane + 32*ii];
            float4 w = w4[lane + 32*ii];
            acc += g.x*w.x + g.y*w.y + g.z*w.z + g.w*w.w;
        }
        #pragma unroll
        for (int o = 16; o; o >>= 1) acc += __shfl_xor_sync(0xffffffffu, acc, o);
        if (lane == 0) {
            float d = 1.f / (1.f + expf(-(acc + b0)));
            float nn = d * anorm;
            int s = 0;
            while (nn > THETA) { nn *= 0.5f; s++; }
            ss[2*wid + rr] = s;
            ys[2*wid + rr] = ldexpf(d, -s);
        }
    }
    float p[NTERMS];
    #pragma unroll
    for (int k = 0; k < NTERMS; k++) p[k] = g_Pd[k*256 + tid];
    __syncthreads();
    #pragma unroll
    for (int r = 0; r < 16; r++) {
        float y = ys[r];
        float acc = p[NTERMS-1];
        #pragma unroll
        for (int k = NTERMS-2; k >= 0; k--) acc = acc*y + p[k];
        Ts[r*257 + tid] = acc;
    }
    __syncthreads();
    int r = tid >> 4, j = tid & 15;
    float v[16];
    #pragma unroll
    for (int i = 0; i < 16; i++) v[i] = Ts[r*257 + i*16 + j];
    int s = ss[r];
    int smax = max(s, __shfl_xor_sync(0xffffffffu, s, 16));
    for (int q = 0; q < smax; q++) {
        float nv[16];
        #pragma unroll
        for (int i = 0; i < 16; i++) nv[i] = 0.f;
        #pragma unroll
        for (int k = 0; k < 16; k++) {
            float w = v[k];
            #pragma unroll
            for (int i = 0; i < 16; i++)
                nv[i] += __shfl_sync(0xffffffffu, v[i], k, 16) * w;
        }
        if (q < s) {
            #pragma unroll
            for (int i = 0; i < 16; i++) v[i] = nv[i];
        }
    }
    float4* o = (float4*)(g_AexpT + (size_t)(r0 + r) * 256 + j * 16);
    o[0] = make_float4(v[0], v[1], v[2], v[3]);
    o[1] = make_float4(v[4], v[5], v[6], v[7]);
    o[2] = make_float4(v[8], v[9], v[10], v[11]);
    o[3] = make_float4(v[12], v[13], v[14], v[15]);
}

// ---------------- kernel 3a: chunk products via tree; ALL 32 leaves loaded up-front ----------------
// Same pairing order as before (identical numerics); dynamic smem, 7 barriers.
__global__ __launch_bounds__(256) void k_chunk() {
    extern __shared__ __align__(16) float sm[];
    float* Em = sm;                 // 48 slots * MS
    float* es = Em + 48*MS;         // 48 * 17
    int gc = blockIdx.x, tid = threadIdx.x;
    int r0 = gc * LCH;
    int q = tid >> 4, i = tid & 15;
    #pragma unroll
    for (int t = 0; t < 32; t++)
        Em[t*MS + tid] = g_AexpT[(size_t)(r0 + t) * 256 + tid];
    #pragma unroll
    for (int idx = tid; idx < 32*16; idx += 256)
        es[(idx >> 4)*17 + (idx & 15)] = g_Bu[(size_t)r0 * NS + idx];
    __syncthreads();
    // L1: 32 leaves -> 16 (slots 32..47)
    comb(Em, es, 2*q, 2*q + 1, 32 + q, i);
    __syncthreads();
    // L2: 16 -> 8 (slots 0..7)
    if (tid < 128) comb(Em, es, 32 + 2*q, 32 + 2*q + 1, q, i);
    __syncthreads();
    // L3: 8 -> 4 (slots 8..11)
    if (tid < 64)  comb(Em, es, 2*q, 2*q + 1, 8 + q, i);
    __syncthreads();
    // L4: 4 -> 2 (slots 12..13)
    if (tid < 32)  comb(Em, es, 8 + 2*q, 8 + 2*q + 1, 12 + q, i);
    __syncthreads();
    // L5: 2 -> 1 (slot 14)
    if (tid < 16)  comb(Em, es, 12, 13, 14, i);
    __syncthreads();
    g_PT[gc * 256 + tid] = Em[14*MS + tid];
    if (tid < 16) g_e[gc * NS + tid] = es[14*17 + tid];
}

// ---------------- kernel 3b-1: supergroup products via tree (parallel, 64 blocks) ----------------
__global__ __launch_bounds__(128) void k_super() {
    __shared__ __align__(16) float Em[15*MS];
    __shared__ float es[15*17];
    int g = blockIdx.x, tid = threadIdx.x;
    int gc0 = g * CPG;
    int q = tid >> 4, i = tid & 15;
    #pragma unroll
    for (int t = 0; t < 8; t++) {
        Em[t*MS + tid]       = g_PT[(gc0 + t)*256 + tid];
        Em[t*MS + tid + 128] = g_PT[(gc0 + t)*256 + tid + 128];
    }
    es[q*17 + i] = g_e[gc0 * NS + tid];
    __syncthreads();
    if (tid < 64) comb(Em, es, 2*q, 2*q + 1, 8 + q, i);
    __syncthreads();
    if (tid < 32) comb(Em, es, 8 + 2*q, 8 + 2*q + 1, 12 + q, i);
    __syncthreads();
    if (tid < 16) comb(Em, es, 12, 13, 14, i);
    __syncthreads();
    g_PTs[g*256 + tid]       = Em[14*MS + tid];
    g_PTs[g*256 + tid + 128] = Em[14*MS + tid + 128];
    if (tid < 16) g_es[g*NS + tid] = es[14*17 + tid];
}

// ---------------- kernel 3b-2: serial combine over 8 supergroups per batch ----------------
__global__ __launch_bounds__(256, 1) void k_comb2() {
    int tid  = threadIdx.x;
    int b    = tid >> 5;
    int lane = tid & 31;
    int m    = lane & 15;
    float h = 0.f;
    int g0 = b * GPB;
    float4 P4[4][4]; float ee[4];
    #pragma unroll
    for (int k = 0; k < 4; k++) {
        const float4* p4 = (const float4*)(g_PTs + (g0 + k) * 256 + m * NS);
        P4[k][0] = p4[0]; P4[k][1] = p4[1]; P4[k][2] = p4[2]; P4[k][3] = p4[3];
        ee[k] = g_es[(g0 + k) * NS + m];
    }
    #pragma unroll
    for (int c = 0; c < GPB; c++) {
        int sl = c & 3;
        int g = g0 + c;
        if (lane < NS) g_hsuper[g * NS + lane] = h;
        float4 p0 = P4[sl][0], p1 = P4[sl][1], p2 = P4[sl][2], p3 = P4[sl][3];
        float e = ee[sl];
        if (c + 4 < GPB) {
            const float4* n4 = (const float4*)(g_PTs + (g + 4) * 256 + m * NS);
            P4[sl][0] = n4[0]; P4[sl][1] = n4[1]; P4[sl][2] = n4[2]; P4[sl][3] = n4[3];
            ee[sl] = g_es[(g + 4) * NS + m];
        }
        float hv[NS];
        #pragma unroll
        for (int n = 0; n < NS; n++) hv[n] = __shfl_sync(0xffffffffu, h, n, 32);
        float t0 = fmaf(hv[0], p0.x, fmaf(hv[1], p0.y, fmaf(hv[2], p0.z, hv[3]*p0.w)));
        float t1 = fmaf(hv[4], p1.x, fmaf(hv[5], p1.y, fmaf(hv[6], p1.z, hv[7]*p1.w)));
        float t2 = fmaf(hv[8], p2.x, fmaf(hv[9], p2.y, fmaf(hv[10], p2.z, hv[11]*p2.w)));
        float t3 = fmaf(hv[12], p3.x, fmaf(hv[13], p3.y, fmaf(hv[14], p3.z, hv[15]*p3.w)));
        h = e + ((t0 + t1) + (t2 + t3));
    }
}

// ---------------- kernel 3c: scan; block = supergroup (8 warps), warp = chunk ----------------
// Warp replays its prefix within the group (<=7 affine steps), then scans its chunk.
__global__ __launch_bounds__(256) void k_scan() {
    int g    = blockIdx.x;
    int wid  = threadIdx.x >> 5;
    int lane = threadIdx.x & 31;
    int m    = lane & 15;
    int gc   = g * CPG + wid;
    int r0   = gc * LCH;
    float h = g_hsuper[g * NS + m];
    for (int k = g * CPG; k < gc; k++) {
        const float4* p4 = (const float4*)(g_PT + k * 256 + m * NS);
        float4 p0 = p4[0], p1 = p4[1], p2 = p4[2], p3 = p4[3];
        float e = g_e[k * NS + m];
        float hv[NS];
        #pragma unroll
        for (int n = 0; n < NS; n++) hv[n] = __shfl_sync(0xffffffffu, h, n, 32);
        float t0 = fmaf(hv[0], p0.x, fmaf(hv[1], p0.y, fmaf(hv[2], p0.z, hv[3]*p0.w)));
        float t1 = fmaf(hv[4], p1.x, fmaf(hv[5], p1.y, fmaf(hv[6], p1.z, hv[7]*p1.w)));
        float t2 = fmaf(hv[8], p2.x, fmaf(hv[9], p2.y, fmaf(hv[10], p2.z, hv[11]*p2.w)));
        float t3 = fmaf(hv[12], p3.x, fmaf(hv[13], p3.y, fmaf(hv[14], p3.z, hv[15]*p3.w)));
        h = e + ((t0 + t1) + (t2 + t3));
    }
    const float4* base = (const float4*)(g_AexpT + (size_t)r0 * 256 + m * NS);
    float4 Ea[4][4]; float bub[4];
    #pragma unroll
    for (int k = 0; k < 4; k++) {
        const float4* p = base + (size_t)k * 64;
        Ea[k][0] = p[0]; Ea[k][1] = p[1]; Ea[k][2] = p[2]; Ea[k][3] = p[3];
        bub[k] = g_Bu[(size_t)(r0 + k) * NS + m];
    }
    #pragma unroll 4
    for (int t = 0; t < LCH; t++) {
        int sl = t & 3;
        float4 a0 = Ea[sl][0], a1 = Ea[sl][1], a2 = Ea[sl][2], a3 = Ea[sl][3];
        float bu = bub[sl];
        if (t + 4 < LCH) {
            const float4* p = base + (size_t)(t + 4) * 64;
            Ea[sl][0] = p[0]; Ea[sl][1] = p[1]; Ea[sl][2] = p[2]; Ea[sl][3] = p[3];
            bub[sl] = g_Bu[(size_t)(r0 + t + 4) * NS + m];
        }
        float hv[NS];
        #pragma unroll
        for (int n = 0; n < NS; n++) hv[n] = __shfl_sync(0xffffffffu, h, n, 32);
        float t0 = fmaf(hv[0], a0.x, fmaf(hv[1], a0.y, fmaf(hv[2], a0.z, hv[3]*a0.w)));
        float t1 = fmaf(hv[4], a1.x, fmaf(hv[5], a1.y, fmaf(hv[6], a1.z, hv[7]*a1.w)));
        float t2 = fmaf(hv[8], a2.x, fmaf(hv[9], a2.y, fmaf(hv[10], a2.z, hv[11]*a2.w)));
        float t3 = fmaf(hv[12], a3.x, fmaf(hv[13], a3.y, fmaf(hv[14], a3.z, hv[15]*a3.w)));
        h = bu + ((t0 + t1) + (t2 + t3));
        if (lane < NS) g_hs[(size_t)(r0 + t) * NS + m] = h;
    }
}

// ---------------- kernel 4: y = hs @ C^T + D*u (32 rows/block, float4 broadcast LDS) ----------------
__global__ __launch_bounds__(256) void k_out(const float* __restrict__ u,
                                             const float* __restrict__ C,
                                             const float* __restrict__ D,
                                             float* __restrict__ y) {
    __shared__ __align__(16) float hs_s[512];
    int tid = threadIdx.x;
    int d   = blockIdx.x * 256 + tid;
    int r0  = blockIdx.y * 32;
    hs_s[tid]       = g_hs[(size_t)r0 * NS + tid];
    hs_s[tid + 256] = g_hs[(size_t)r0 * NS + tid + 256];
    const float4* c4 = (const float4*)(C + (size_t)d * NS);
    float4 c0 = c4[0], c1 = c4[1], c2 = c4[2], c3 = c4[3];
    float Dd = D[d];
    float ucur = u[(size_t)r0 * DIM + d];
    __syncthreads();
    #pragma unroll 8
    for (int sl = 0; sl < 32; sl++) {
        float unext = 0.f;
        if (sl + 1 < 32) unext = u[(size_t)(r0 + sl + 1) * DIM + d];
        const float4* hp = (const float4*)(hs_s + sl * 16);
        float4 h0 = hp[0], h1 = hp[1], h2 = hp[2], h3 = hp[3];
        float t0 = fmaf(h0.x, c0.x, fmaf(h0.y, c0.y, fmaf(h0.z, c0.z, h0.w*c0.w)));
        float t1 = fmaf(h1.x, c1.x, fmaf(h1.y, c1.y, fmaf(h1.z, c1.z, h1.w*c1.w)));
        float t2 = fmaf(h2.x, c2.x, fmaf(h2.y, c2.y, fmaf(h2.z, c2.z, h2.w*c2.w)));
        float t3 = fmaf(h3.x, c3.x, fmaf(h3.y, c3.y, fmaf(h3.z, c3.z, h3.w*c3.w)));
        y[(size_t)(r0 + sl) * DIM + d] = Dd * ucur + ((t0 + t1) + (t2 + t3));
        ucur = unext;
    }
}

// ---------------- launch ----------------
extern "C" void kernel_launch(void* const* d_in, const int* in_sizes, int n_in,
                              void* d_out, int out_size) {
    const float* u     = (const float*)d_in[0];
    const float* gate  = (const float*)d_in[1];
    const float* A_log = (const float*)d_in[2];
    const float* B_mat = (const float*)d_in[3];
    const float* C_mat = (const float*)d_in[4];
    const float* D     = (const float*)d_in[5];
    const float* dt_w  = (const float*)d_in[6];
    const float* dt_b  = (const float*)d_in[7];
    float* y = (float*)d_out;

    cudaFuncSetAttribute(k_chunk, cudaFuncAttributeMaxDynamicSharedMemorySize, CHUNK_SMEM_BYTES);

    k_prepA<<<1, 256>>>(A_log);
    k_bu<<<ROWS/128, 256>>>(u, B_mat);
    k_expm<<<ROWS/16, 256>>>(gate, dt_w, dt_b);
    k_chunk<<<NCHUNK, 256, CHUNK_SMEM_BYTES>>>();
    k_super<<<NGRP, 128>>>();
    k_comb2<<<1, 256>>>();
    k_scan<<<NGRP, 256>>>();
    k_out<<<dim3(DIM/256, ROWS/32), 256>>>(u, C_mat, D, y);
}

// round 17
// speedup vs baseline: 1.2319x; 1.1936x over previous
#include <cuda_runtime.h>

#define BATCHN 8
#define SEQ    2048
#define DIM    1024
#define NS     16
#define ROWS   (BATCHN*SEQ)     // 16384
#define LCH    32               // chunk length
#define CPB    (SEQ/LCH)        // 64 chunks per batch
#define NCHUNK (BATCHN*CPB)     // 512 chunks
#define GPB    8                // supergroups per batch
#define CPG    (CPB/GPB)        // 8 chunks per supergroup
#define NGRP   (BATCHN*GPB)     // 64 supergroups
#define NTERMS 21               // Taylor degree 20
#define THETA  5.2f
#define MS     260              // shared matrix slot stride (floats)
#define NBU    (ROWS/128)       // 128 bu blocks
#define NEXPM  (ROWS/16)        // 1024 expm blocks

// ---------------- scratch (static device globals; no runtime alloc) ----------------
__device__ float g_Anorm;
__device__ __align__(128) float g_Pd[NTERMS*256];              // A^k / k!
__device__ __align__(128) float g_Bu[ROWS*NS];
__device__ __align__(128) float g_AexpT[(size_t)ROWS*NS*NS];   // 16 MB, E^T per row
__device__ __align__(128) float g_PT[NCHUNK*NS*NS];            // chunk product transposed
__device__ __align__(128) float g_e[NCHUNK*NS];                // chunk end-state
__device__ __align__(128) float g_PTs[NGRP*NS*NS];             // supergroup product
__device__ __align__(128) float g_es[NGRP*NS];                 // supergroup end-state
__device__ __align__(128) float g_hsuper[NGRP*NS];             // state at supergroup start
__device__ __align__(128) float g_hstart[NCHUNK*NS];           // state at chunk start
__device__ __align__(128) float g_hs[(size_t)ROWS*NS];

// ---------------- f32x2 helpers ----------------
__device__ __forceinline__ unsigned long long pk2(float lo, float hi) {
    unsigned long long r;
    asm("mov.b64 %0, {%1, %2};" : "=l"(r) : "f"(lo), "f"(hi));
    return r;
}
__device__ __forceinline__ float2 upk2(unsigned long long v) {
    float2 r;
    asm("mov.b64 {%0, %1}, %2;" : "=f"(r.x), "=f"(r.y) : "l"(v));
    return r;
}
__device__ __forceinline__ void fma2(unsigned long long& d, unsigned long long a, unsigned long long b) {
    asm("fma.rn.f32x2 %0, %1, %2, %0;" : "+l"(d) : "l"(a), "l"(b));
}

// ---------------- combine: S_out = S_R @ S_L, e_out = S_R e_L + e_R ----------------
__device__ __forceinline__ void comb(float* Em, float* es, int sL, int sR, int sO, int i) {
    const float* A = &Em[sR*MS + i*16];
    const float* B = &Em[sL*MS];
    float a[16];
    #pragma unroll
    for (int k = 0; k < 16; k++) a[k] = A[k];
    float4 c0 = make_float4(0,0,0,0), c1 = c0, c2 = c0, c3 = c0;
    #pragma unroll
    for (int k = 0; k < 16; k++) {
        const float4* bk = (const float4*)(B + k*16);
        float4 b0 = bk[0], b1 = bk[1], b2 = bk[2], b3 = bk[3];
        float w = a[k];
        c0.x = fmaf(w, b0.x, c0.x); c0.y = fmaf(w, b0.y, c0.y);
        c0.z = fmaf(w, b0.z, c0.z); c0.w = fmaf(w, b0.w, c0.w);
        c1.x = fmaf(w, b1.x, c1.x); c1.y = fmaf(w, b1.y, c1.y);
        c1.z = fmaf(w, b1.z, c1.z); c1.w = fmaf(w, b1.w, c1.w);
        c2.x = fmaf(w, b2.x, c2.x); c2.y = fmaf(w, b2.y, c2.y);
        c2.z = fmaf(w, b2.z, c2.z); c2.w = fmaf(w, b2.w, c2.w);
        c3.x = fmaf(w, b3.x, c3.x); c3.y = fmaf(w, b3.y, c3.y);
        c3.z = fmaf(w, b3.z, c3.z); c3.w = fmaf(w, b3.w, c3.w);
    }
    const float* eL = &es[sL*17];
    float ev = es[sR*17 + i];
    #pragma unroll
    for (int k = 0; k < 16; k++) ev = fmaf(a[k], eL[k], ev);
    float4* C4 = (float4*)&Em[sO*MS + i*16];
    C4[0] = c0; C4[1] = c1; C4[2] = c2; C4[3] = c3;
    es[sO*17 + i] = ev;
}

// ---------------- kernel 0: A = -exp(A_log), inf-norm, P_k = A^k/k! ----------------
__global__ __launch_bounds__(256) void k_prepA(const float* __restrict__ A_log) {
    __shared__ float As[256];
    __shared__ float buf[2][256];
    __shared__ float rowsum[NS];
    int tid = threadIdx.x;
    int i = tid >> 4, j = tid & 15;
    float a = -expf(A_log[tid]);
    As[tid] = a;
    __syncthreads();
    float Ac[16];
    #pragma unroll
    for (int k = 0; k < 16; k++) Ac[k] = As[k*16 + j];
    if (tid < NS) {
        float s = 0.f;
        #pragma unroll
        for (int c = 0; c < NS; c++) s += fabsf(As[tid*16 + c]);
        rowsum[tid] = s;
    }
    __syncthreads();
    if (tid == 0) {
        float m = 0.f;
        #pragma unroll
        for (int r = 0; r < NS; r++) m = fmaxf(m, rowsum[r]);
        g_Anorm = m;
    }
    float id = (i == j) ? 1.f : 0.f;
    buf[0][tid] = id;
    g_Pd[tid] = id;
    __syncthreads();
    int cur = 0;
    for (int k = 1; k < NTERMS; k++) {
        const float* row = &buf[cur][i*16];
        float a0 = fmaf(row[0], Ac[0], fmaf(row[1], Ac[1], fmaf(row[2], Ac[2], row[3]*Ac[3])));
        float a1 = fmaf(row[4], Ac[4], fmaf(row[5], Ac[5], fmaf(row[6], Ac[6], row[7]*Ac[7])));
        float a2 = fmaf(row[8], Ac[8], fmaf(row[9], Ac[9], fmaf(row[10], Ac[10], row[11]*Ac[11])));
        float a3 = fmaf(row[12], Ac[12], fmaf(row[13], Ac[13], fmaf(row[14], Ac[14], row[15]*Ac[15])));
        float acc = ((a0 + a1) + (a2 + a3)) * (1.f / (float)k);
        buf[cur ^ 1][tid] = acc;
        g_Pd[k*256 + tid] = acc;
        cur ^= 1;
        __syncthreads();
    }
}

// ---------------- fused front-end: blocks 0..NBU-1 = Bu GEMM, NBU.. = delta+expm ----------------
union __align__(16) SmemU {
    struct { float usb[128*33]; float Bst[16*34]; } bu;
    struct { float Ts[16*257]; float ys[16]; int ss[16]; } ex;
};

__global__ __launch_bounds__(256, 1) void k_front(const float* __restrict__ u,
                                                  const float* __restrict__ B,
                                                  const float* __restrict__ gate,
                                                  const float* __restrict__ dt_w,
                                                  const float* __restrict__ dt_b) {
    __shared__ SmemU sm;
    int tid = threadIdx.x;
    if (blockIdx.x < NBU) {
        // ================= Bu = u @ B_mat =================
        float* usb = sm.bu.usb;
        float* Bst = sm.bu.Bst;
        int ks   = tid >> 7;
        int ngrp = (tid >> 6) & 1;
        int rowp = tid & 63;
        int r0   = blockIdx.x * 128;

        unsigned long long a0[8], a1[8];
        #pragma unroll
        for (int nn = 0; nn < 8; nn++) { a0[nn] = 0ull; a1[nn] = 0ull; }

        int lrow = tid >> 3, lq = tid & 7;
        int bkk  = tid >> 3, bnp = tid & 7;
        float4 pu[4]; float2 pb;
        #pragma unroll
        for (int it = 0; it < 4; it++)
            pu[it] = *(const float4*)&u[(size_t)(r0 + lrow + it*32) * DIM + lq*4];
        pb = *(const float2*)&B[(size_t)bkk * NS + bnp*2];

        for (int t = 0; t < 32; t++) {
            #pragma unroll
            for (int it = 0; it < 4; it++) {
                int row = lrow + it*32;
                usb[row*33 + lq*4 + 0] = pu[it].x;
                usb[row*33 + lq*4 + 1] = pu[it].y;
                usb[row*33 + lq*4 + 2] = pu[it].z;
                usb[row*33 + lq*4 + 3] = pu[it].w;
            }
            Bst[(2*bnp + 0)*34 + bkk] = pb.x;
            Bst[(2*bnp + 1)*34 + bkk] = pb.y;
            __syncthreads();
            if (t + 1 < 32) {
                int kt = (t + 1) * 32;
                #pragma unroll
                for (int it = 0; it < 4; it++)
                    pu[it] = *(const float4*)&u[(size_t)(r0 + lrow + it*32) * DIM + kt + lq*4];
                pb = *(const float2*)&B[(size_t)(kt + bkk) * NS + bnp*2];
            }
            int kb = ks * 16;
            #pragma unroll
            for (int kk = 0; kk < 8; kk++) {
                int k = kb + 2*kk;
                unsigned long long ua = *(const unsigned long long*)&usb[(2*rowp)*33 + k];
                const float* ur1 = &usb[(2*rowp + 1)*33 + k];
                unsigned long long ub = pk2(ur1[0], ur1[1]);
                #pragma unroll
                for (int nn = 0; nn < 8; nn++) {
                    unsigned long long bb = *(const unsigned long long*)&Bst[(8*ngrp + nn)*34 + k];
                    fma2(a0[nn], ua, bb);
                    fma2(a1[nn], ub, bb);
                }
            }
            __syncthreads();
        }
        float* red = usb;
        if (ks == 1) {
            int p = tid - 128;
            #pragma unroll
            for (int nn = 0; nn < 8; nn++) {
                float2 x0 = upk2(a0[nn]); float2 x1 = upk2(a1[nn]);
                red[p*16 + nn]     = x0.x + x0.y;
                red[p*16 + 8 + nn] = x1.x + x1.y;
            }
        }
        __syncthreads();
        if (ks == 0) {
            #pragma unroll
            for (int nn = 0; nn < 8; nn++) {
                float2 x0 = upk2(a0[nn]); float2 x1 = upk2(a1[nn]);
                float v0 = x0.x + x0.y + red[tid*16 + nn];
                float v1 = x1.x + x1.y + red[tid*16 + 8 + nn];
                g_Bu[(size_t)(r0 + 2*rowp)     * NS + 8*ngrp + nn] = v0;
                g_Bu[(size_t)(r0 + 2*rowp + 1) * NS + 8*ngrp + nn] = v1;
            }
        }
    } else {
        // ================= delta + expm =================
        float* Ts = sm.ex.Ts;
        float* ys = sm.ex.ys;
        int*   ss = sm.ex.ss;
        int r0 = (blockIdx.x - NBU) * 16;
        int wid = tid >> 5, lane = tid & 31;
        const float4* w4 = (const float4*)dt_w;
        float anorm = g_Anorm;
        float b0 = dt_b[0];
        #pragma unroll
        for (int rr = 0; rr < 2; rr++) {
            int row = r0 + 2*wid + rr;
            const float4* g4 = (const float4*)(gate + (size_t)row * DIM);
            float acc = 0.f;
            #pragma unroll
            for (int ii = 0; ii < 8; ii++) {
                float4 g = g4[lane + 32*ii];
                float4 w = w4[lane + 32*ii];
                acc += g.x*w.x + g.y*w.y + g.z*w.z + g.w*w.w;
            }
            #pragma unroll
            for (int o = 16; o; o >>= 1) acc += __shfl_xor_sync(0xffffffffu, acc, o);
            if (lane == 0) {
                float d = 1.f / (1.f + expf(-(acc + b0)));
                float nn = d * anorm;
                int s = 0;
                while (nn > THETA) { nn *= 0.5f; s++; }
                ss[2*wid + rr] = s;
                ys[2*wid + rr] = ldexpf(d, -s);
            }
        }
        float p[NTERMS];
        #pragma unroll
        for (int k = 0; k < NTERMS; k++) p[k] = g_Pd[k*256 + tid];
        __syncthreads();
        #pragma unroll
        for (int r = 0; r < 16; r++) {
            float y = ys[r];
            float acc = p[NTERMS-1];
            #pragma unroll
            for (int k = NTERMS-2; k >= 0; k--) acc = acc*y + p[k];
            Ts[r*257 + tid] = acc;
        }
        __syncthreads();
        int r = tid >> 4, j = tid & 15;
        float v[16];
        #pragma unroll
        for (int i = 0; i < 16; i++) v[i] = Ts[r*257 + i*16 + j];
        int s = ss[r];
        int smax = max(s, __shfl_xor_sync(0xffffffffu, s, 16));
        for (int q = 0; q < smax; q++) {
            float nv[16];
            #pragma unroll
            for (int i = 0; i < 16; i++) nv[i] = 0.f;
            #pragma unroll
            for (int k = 0; k < 16; k++) {
                float w = v[k];
                #pragma unroll
                for (int i = 0; i < 16; i++)
                    nv[i] += __shfl_sync(0xffffffffu, v[i], k, 16) * w;
            }
            if (q < s) {
                #pragma unroll
                for (int i = 0; i < 16; i++) v[i] = nv[i];
            }
        }
        float4* o = (float4*)(g_AexpT + (size_t)(r0 + r) * 256 + j * 16);
        o[0] = make_float4(v[0], v[1], v[2], v[3]);
        o[1] = make_float4(v[4], v[5], v[6], v[7]);
        o[2] = make_float4(v[8], v[9], v[10], v[11]);
        o[3] = make_float4(v[12], v[13], v[14], v[15]);
    }
}

// ---------------- kernel 3a: chunk products via balanced tree (R11 proven, two-stage) ----------------
__global__ __launch_bounds__(256) void k_chunk() {
    __shared__ __align__(16) float Em[32*MS];
    __shared__ float es[32*17];
    int gc = blockIdx.x, tid = threadIdx.x;
    int r0 = gc * LCH;
    int q = tid >> 4, i = tid & 15;
    #pragma unroll
    for (int t = 0; t < 16; t++)
        Em[t*MS + tid] = g_AexpT[(size_t)(r0 + t) * 256 + tid];
    for (int idx = tid; idx < 16*16; idx += 256)
        es[(idx >> 4)*17 + (idx & 15)] = g_Bu[(size_t)r0 * NS + idx];
    __syncthreads();
    if (tid < 128) comb(Em, es, 2*q, 2*q + 1, 16 + q, i);
    __syncthreads();
    #pragma unroll
    for (int t = 0; t < 16; t++)
        Em[t*MS + tid] = g_AexpT[(size_t)(r0 + 16 + t) * 256 + tid];
    for (int idx = tid; idx < 16*16; idx += 256)
        es[(idx >> 4)*17 + (idx & 15)] = g_Bu[(size_t)(r0 + 16) * NS + idx];
    __syncthreads();
    if (tid < 128) comb(Em, es, 2*q, 2*q + 1, 24 + q, i);
    __syncthreads();
    if (tid < 128) comb(Em, es, 16 + 2*q, 16 + 2*q + 1, q, i);
    __syncthreads();
    if (tid < 64)  comb(Em, es, 2*q, 2*q + 1, 16 + q, i);
    __syncthreads();
    if (tid < 32)  comb(Em, es, 16 + 2*q, 16 + 2*q + 1, q, i);
    __syncthreads();
    if (tid < 16)  comb(Em, es, 0, 1, 16, i);
    __syncthreads();
    g_PT[gc * 256 + tid] = Em[16*MS + tid];
    if (tid < 16) g_e[gc * NS + tid] = es[16*17 + tid];
}

// ---------------- kernel 3b-1: supergroup products via tree (parallel, 64 blocks) ----------------
__global__ __launch_bounds__(128) void k_super() {
    __shared__ __align__(16) float Em[15*MS];
    __shared__ float es[15*17];
    int g = blockIdx.x, tid = threadIdx.x;
    int gc0 = g * CPG;
    int q = tid >> 4, i = tid & 15;
    #pragma unroll
    for (int t = 0; t < 8; t++) {
        Em[t*MS + tid]       = g_PT[(gc0 + t)*256 + tid];
        Em[t*MS + tid + 128] = g_PT[(gc0 + t)*256 + tid + 128];
    }
    es[q*17 + i] = g_e[gc0 * NS + tid];
    __syncthreads();
    if (tid < 64) comb(Em, es, 2*q, 2*q + 1, 8 + q, i);
    __syncthreads();
    if (tid < 32) comb(Em, es, 8 + 2*q, 8 + 2*q + 1, 12 + q, i);
    __syncthreads();
    if (tid < 16) comb(Em, es, 12, 13, 14, i);
    __syncthreads();
    g_PTs[g*256 + tid]       = Em[14*MS + tid];
    g_PTs[g*256 + tid + 128] = Em[14*MS + tid + 128];
    if (tid < 16) g_es[g*NS + tid] = es[14*17 + tid];
}

// ---------------- kernel 3b-2: serial combine over 8 supergroups per batch ----------------
__global__ __launch_bounds__(256, 1) void k_comb2() {
    int tid  = threadIdx.x;
    int b    = tid >> 5;
    int lane = tid & 31;
    int m    = lane & 15;
    float h = 0.f;
    int g0 = b * GPB;
    float4 P4[4][4]; float ee[4];
    #pragma unroll
    for (int k = 0; k < 4; k++) {
        const float4* p4 = (const float4*)(g_PTs + (g0 + k) * 256 + m * NS);
        P4[k][0] = p4[0]; P4[k][1] = p4[1]; P4[k][2] = p4[2]; P4[k][3] = p4[3];
        ee[k] = g_es[(g0 + k) * NS + m];
    }
    #pragma unroll
    for (int c = 0; c < GPB; c++) {
        int sl = c & 3;
        int g = g0 + c;
        if (lane < NS) g_hsuper[g * NS + lane] = h;
        float4 p0 = P4[sl][0], p1 = P4[sl][1], p2 = P4[sl][2], p3 = P4[sl][3];
        float e = ee[sl];
        if (c + 4 < GPB) {
            const float4* n4 = (const float4*)(g_PTs + (g + 4) * 256 + m * NS);
            P4[sl][0] = n4[0]; P4[sl][1] = n4[1]; P4[sl][2] = n4[2]; P4[sl][3] = n4[3];
            ee[sl] = g_es[(g + 4) * NS + m];
        }
        float hv[NS];
        #pragma unroll
        for (int n = 0; n < NS; n++) hv[n] = __shfl_sync(0xffffffffu, h, n, 32);
        float t0 = fmaf(hv[0], p0.x, fmaf(hv[1], p0.y, fmaf(hv[2], p0.z, hv[3]*p0.w)));
        float t1 = fmaf(hv[4], p1.x, fmaf(hv[5], p1.y, fmaf(hv[6], p1.z, hv[7]*p1.w)));
        float t2 = fmaf(hv[8], p2.x, fmaf(hv[9], p2.y, fmaf(hv[10], p2.z, hv[11]*p2.w)));
        float t3 = fmaf(hv[12], p3.x, fmaf(hv[13], p3.y, fmaf(hv[14], p3.z, hv[15]*p3.w)));
        h = e + ((t0 + t1) + (t2 + t3));
    }
}

// ---------------- kernel 3b-3: chunk start states within each supergroup (parallel, 64 warps) ----------------
__global__ __launch_bounds__(32) void k_hstart() {
    int g    = blockIdx.x;
    int lane = threadIdx.x & 31;
    int m    = lane & 15;
    int gc0  = g * CPG;
    float h = g_hsuper[g * NS + m];
    float4 P4[4][4]; float ee[4];
    #pragma unroll
    for (int k = 0; k < 4; k++) {
        const float4* p4 = (const float4*)(g_PT + (gc0 + k) * 256 + m * NS);
        P4[k][0] = p4[0]; P4[k][1] = p4[1]; P4[k][2] = p4[2]; P4[k][3] = p4[3];
        ee[k] = g_e[(gc0 + k) * NS + m];
    }
    #pragma unroll
    for (int c = 0; c < CPG; c++) {
        int sl = c & 3;
        int gc = gc0 + c;
        if (lane < NS) g_hstart[gc * NS + lane] = h;
        float4 p0 = P4[sl][0], p1 = P4[sl][1], p2 = P4[sl][2], p3 = P4[sl][3];
        float e = ee[sl];
        if (c + 4 < CPG) {
            const float4* n4 = (const float4*)(g_PT + (gc + 4) * 256 + m * NS);
            P4[sl][0] = n4[0]; P4[sl][1] = n4[1]; P4[sl][2] = n4[2]; P4[sl][3] = n4[3];
            ee[sl] = g_e[(gc + 4) * NS + m];
        }
        float hv[NS];
        #pragma unroll
        for (int n = 0; n < NS; n++) hv[n] = __shfl_sync(0xffffffffu, h, n, 32);
        float t0 = fmaf(hv[0], p0.x, fmaf(hv[1], p0.y, fmaf(hv[2], p0.z, hv[3]*p0.w)));
        float t1 = fmaf(hv[4], p1.x, fmaf(hv[5], p1.y, fmaf(hv[6], p1.z, hv[7]*p1.w)));
        float t2 = fmaf(hv[8], p2.x, fmaf(hv[9], p2.y, fmaf(hv[10], p2.z, hv[11]*p2.w)));
        float t3 = fmaf(hv[12], p3.x, fmaf(hv[13], p3.y, fmaf(hv[14], p3.z, hv[15]*p3.w)));
        h = e + ((t0 + t1) + (t2 + t3));
    }
}

// ---------------- kernel 3c: per-chunk matvec scan, 4-deep prefetch (512 blocks) ----------------
__global__ __launch_bounds__(32) void k_scan() {
    int gc   = blockIdx.x;
    int lane = threadIdx.x & 31;
    int m    = lane & 15;
    int r0   = gc * LCH;
    float h = g_hstart[gc * NS + m];
    const float4* base = (const float4*)(g_AexpT + (size_t)r0 * 256 + m * NS);
    float4 Ea[4][4]; float bub[4];
    #pragma unroll
    for (int k = 0; k < 4; k++) {
        const float4* p = base + (size_t)k * 64;
        Ea[k][0] = p[0]; Ea[k][1] = p[1]; Ea[k][2] = p[2]; Ea[k][3] = p[3];
        bub[k] = g_Bu[(size_t)(r0 + k) * NS + m];
    }
    #pragma unroll 4
    for (int t = 0; t < LCH; t++) {
        int sl = t & 3;
        float4 a0 = Ea[sl][0], a1 = Ea[sl][1], a2 = Ea[sl][2], a3 = Ea[sl][3];
        float bu = bub[sl];
        if (t + 4 < LCH) {
            const float4* p = base + (size_t)(t + 4) * 64;
            Ea[sl][0] = p[0]; Ea[sl][1] = p[1]; Ea[sl][2] = p[2]; Ea[sl][3] = p[3];
            bub[sl] = g_Bu[(size_t)(r0 + t + 4) * NS + m];
        }
        float hv[NS];
        #pragma unroll
        for (int n = 0; n < NS; n++) hv[n] = __shfl_sync(0xffffffffu, h, n, 32);
        float t0 = fmaf(hv[0], a0.x, fmaf(hv[1], a0.y, fmaf(hv[2], a0.z, hv[3]*a0.w)));
        float t1 = fmaf(hv[4], a1.x, fmaf(hv[5], a1.y, fmaf(hv[6], a1.z, hv[7]*a1.w)));
        float t2 = fmaf(hv[8], a2.x, fmaf(hv[9], a2.y, fmaf(hv[10], a2.z, hv[11]*a2.w)));
        float t3 = fmaf(hv[12], a3.x, fmaf(hv[13], a3.y, fmaf(hv[14], a3.z, hv[15]*a3.w)));
        h = bu + ((t0 + t1) + (t2 + t3));
        if (lane < NS) g_hs[(size_t)(r0 + t) * NS + m] = h;
    }
}

// ---------------- kernel 4: y = hs @ C^T + D*u (32 rows/block, float4 broadcast LDS) ----------------
__global__ __launch_bounds__(256) void k_out(const float* __restrict__ u,
                                             const float* __restrict__ C,
                                             const float* __restrict__ D,
                                             float* __restrict__ y) {
    __shared__ __align__(16) float hs_s[512];
    int tid = threadIdx.x;
    int d   = blockIdx.x * 256 + tid;
    int r0  = blockIdx.y * 32;
    hs_s[tid]       = g_hs[(size_t)r0 * NS + tid];
    hs_s[tid + 256] = g_hs[(size_t)r0 * NS + tid + 256];
    const float4* c4 = (const float4*)(C + (size_t)d * NS);
    float4 c0 = c4[0], c1 = c4[1], c2 = c4[2], c3 = c4[3];
    float Dd = D[d];
    float ucur = u[(size_t)r0 * DIM + d];
    __syncthreads();
    #pragma unroll 8
    for (int sl = 0; sl < 32; sl++) {
        float unext = 0.f;
        if (sl + 1 < 32) unext = u[(size_t)(r0 + sl + 1) * DIM + d];
        const float4* hp = (const float4*)(hs_s + sl * 16);
        float4 h0 = hp[0], h1 = hp[1], h2 = hp[2], h3 = hp[3];
        float t0 = fmaf(h0.x, c0.x, fmaf(h0.y, c0.y, fmaf(h0.z, c0.z, h0.w*c0.w)));
        float t1 = fmaf(h1.x, c1.x, fmaf(h1.y, c1.y, fmaf(h1.z, c1.z, h1.w*c1.w)));
        float t2 = fmaf(h2.x, c2.x, fmaf(h2.y, c2.y, fmaf(h2.z, c2.z, h2.w*c2.w)));
        float t3 = fmaf(h3.x, c3.x, fmaf(h3.y, c3.y, fmaf(h3.z, c3.z, h3.w*c3.w)));
        y[(size_t)(r0 + sl) * DIM + d] = Dd * ucur + ((t0 + t1) + (t2 + t3));
        ucur = unext;
    }
}

// ---------------- launch ----------------
extern "C" void kernel_launch(void* const* d_in, const int* in_sizes, int n_in,
                              void* d_out, int out_size) {
    const float* u     = (const float*)d_in[0];
    const float* gate  = (const float*)d_in[1];
    const float* A_log = (const float*)d_in[2];
    const float* B_mat = (const float*)d_in[3];
    const float* C_mat = (const float*)d_in[4];
    const float* D     = (const float*)d_in[5];
    const float* dt_w  = (const float*)d_in[6];
    const float* dt_b  = (const float*)d_in[7];
    float* y = (float*)d_out;

    k_prepA<<<1, 256>>>(A_log);
    k_front<<<NBU + NEXPM, 256>>>(u, B_mat, gate, dt_w, dt_b);
    k_chunk<<<NCHUNK, 256>>>();
    k_super<<<NGRP, 128>>>();
    k_comb2<<<1, 256>>>();
    k_hstart<<<NGRP, 32>>>();
    k_scan<<<NCHUNK, 32>>>();
    k_out<<<dim3(DIM/256, ROWS/32), 256>>>(u, C_mat, D, y);
}